// round 9
// baseline (speedup 1.0000x reference)
#include <cuda_runtime.h>
#include <cuda_fp16.h>
#include <math.h>

#define NUM_INITS 64
#define PSTRIDE   46922
#define OFF_WDENSE 832
#define OFF_BDENSE 46912

// Dense weights pre-swizzled into fp16 B-fragment order:
// [init][wg(2)][w(144)][lane(32)] -> uint4 {b0_nt0, b1_nt0, b0_nt1, b1_nt1}
__device__ uint4 g_wdh[128 * 144 * 32];   // 9.4 MB

__device__ __forceinline__ unsigned pack_h2(float lo, float hi) {
    __half2 h = __floats2half2_rn(lo, hi);
    return *(unsigned*)&h;
}

__device__ __forceinline__ unsigned tf32_of(float x) {
    unsigned r;
    asm("cvt.rna.tf32.f32 %0, %1;" : "=r"(r) : "f"(x));
    return r;
}

#define MMA_TF32(c0,c1,c2,c3,a0,a1,a2,a3,b0,b1) \
    asm("mma.sync.aligned.m16n8k8.row.col.f32.tf32.tf32.f32 " \
        "{%0,%1,%2,%3}, {%4,%5,%6,%7}, {%8,%9}, {%0,%1,%2,%3};" \
        : "+f"(c0), "+f"(c1), "+f"(c2), "+f"(c3) \
        : "r"(a0), "r"(a1), "r"(a2), "r"(a3), "r"(b0), "r"(b1))

#define MMA_F16(c0,c1,c2,c3,a0,a1,a2,a3,b0,b1) \
    asm("mma.sync.aligned.m16n8k16.row.col.f32.f16.f16.f32 " \
        "{%0,%1,%2,%3}, {%4,%5,%6,%7}, {%8,%9}, {%0,%1,%2,%3};" \
        : "+f"(c0), "+f"(c1), "+f"(c2), "+f"(c3) \
        : "r"(a0), "r"(a1), "r"(a2), "r"(a3), "r"(b0), "r"(b1))

// ============================================================================
// Prep: swizzle dense weights -> fp16 B fragments. grid 128 = (init, wg)
// ============================================================================
__global__ void __launch_bounds__(256)
prep_wd_kernel(const float* __restrict__ params)
{
    const int blk  = blockIdx.x;          // init*2 + wg
    const int init = blk >> 1;
    const int wg   = blk & 1;
    const float* __restrict__ W = params + (size_t)init * PSTRIDE + OFF_WDENSE;

    for (int u = threadIdx.x; u < 144 * 32; u += 256) {
        int w    = u >> 5;
        int lane = u & 31;
        int g    = lane >> 2;
        int tb   = lane & 3;
        int ch0  = wg * 16 + 2 * tb;

        #define WD(o, ch) W[(size_t)(o) * 4608 + (ch) * 144 + w]
        unsigned b0n0 = pack_h2(WD(g, ch0),     WD(g, ch0 + 1));
        unsigned b1n0 = pack_h2(WD(g, ch0 + 8), WD(g, ch0 + 9));
        unsigned b0n1 = 0, b1n1 = 0;
        if (g + 8 < 10) {
            b0n1 = pack_h2(WD(g + 8, ch0),     WD(g + 8, ch0 + 1));
            b1n1 = pack_h2(WD(g + 8, ch0 + 8), WD(g + 8, ch0 + 9));
        }
        #undef WD
        g_wdh[(size_t)(blk * 144 + w) * 32 + lane] =
            make_uint4(b0n0, b1n0, b0n1, b1n1);
    }
}

// ============================================================================
// Fused: conv5x5(tf32 3-pass, hi/lo precomputed in smem) + pool + bias + relu
//        + dense(fp16 mma) + log_softmax
// grid 512 = (init, img-tile of 16), 384 threads = 12 warps
// ============================================================================
#define IMG_STR 788
#define K1_THREADS 384
#define K1_SMEM (2 * 16 * IMG_STR * 4)    // hi + lo planes = 100864 B

__global__ void __launch_bounds__(K1_THREADS, 2)
fused_kernel(const float* __restrict__ params,
             const float* __restrict__ batch,
             float* __restrict__ out)
{
    extern __shared__ unsigned s_mem[];
    unsigned* s_hi = s_mem;                   // [16][788] tf32 hi bits
    unsigned* s_lo = s_mem + 16 * IMG_STR;    // [16][788] tf32 lo bits

    const int blk  = blockIdx.x;
    const int init = blk >> 3;
    const int n0   = (blk & 7) * 16;
    const int t    = threadIdx.x;
    const int warp = t >> 5;
    const int lane = t & 31;
    const int g    = lane >> 2;   // 0..7
    const int tid  = lane & 3;    // 0..3

    const float* __restrict__ P = params + (size_t)init * PSTRIDE;

    // ---- stage 16 images, splitting each pixel into tf32 hi/lo once ----
    for (int u = t; u < 16 * 196; u += K1_THREADS) {
        int img = u / 196, q = u - img * 196;
        float4 v = ((const float4*)(batch + (size_t)(n0 + img) * 784))[q];
        uint4 hi, lo;
        hi.x = tf32_of(v.x); lo.x = tf32_of(v.x - __uint_as_float(hi.x));
        hi.y = tf32_of(v.y); lo.y = tf32_of(v.y - __uint_as_float(hi.y));
        hi.z = tf32_of(v.z); lo.z = tf32_of(v.z - __uint_as_float(hi.z));
        hi.w = tf32_of(v.w); lo.w = tf32_of(v.w - __uint_as_float(hi.w));
        ((uint4*)(s_hi + img * IMG_STR))[q] = hi;
        ((uint4*)(s_lo + img * IMG_STR))[q] = lo;
    }
    __syncthreads();

    const int wg     = warp / 6;          // channels wg*16..+15
    const int widx   = warp % 6;          // windows widx*24..+23
    const int chbase = wg * 16;

    // ---- conv B fragments (weights), split hi/lo ----
    unsigned bhi[2][3][2], blo[2][3][2];
    #pragma unroll
    for (int nt = 0; nt < 2; ++nt) {
        int ch = chbase + nt * 8 + g;
        #pragma unroll
        for (int s = 0; s < 3; ++s) {
            float w0 = P[ch * 25 + s * 8 + tid];
            float w1 = P[ch * 25 + s * 8 + tid + 4];
            unsigned h0 = tf32_of(w0), h1 = tf32_of(w1);
            bhi[nt][s][0] = h0;
            bhi[nt][s][1] = h1;
            blo[nt][s][0] = tf32_of(w0 - __uint_as_float(h0));
            blo[nt][s][1] = tf32_of(w1 - __uint_as_float(h1));
        }
    }
    float w24[2][2], cbias[2][2];
    #pragma unroll
    for (int nt = 0; nt < 2; ++nt)
        #pragma unroll
        for (int jj = 0; jj < 2; ++jj) {
            int ch = chbase + nt * 8 + 2 * tid + jj;
            w24[nt][jj]   = P[ch * 25 + 24];
            cbias[nt][jj] = P[800 + ch];
        }

    int koffA[3], koffB[3];
    #pragma unroll
    for (int s = 0; s < 3; ++s) {
        int ka = s * 8 + tid, kb = ka + 4;
        koffA[s] = (ka / 5) * 28 + (ka % 5);
        koffB[s] = (kb / 5) * 28 + (kb % 5);
    }

    const uint4* __restrict__ wdfrag =
        g_wdh + (size_t)((init * 2 + wg) * 144) * 32 + lane;

    // persistent dense accumulators
    float dc[2][4];
    #pragma unroll
    for (int q = 0; q < 4; ++q) { dc[0][q] = 0.f; dc[1][q] = 0.f; }

    // ---- main loop over this warp's 24 pool windows ----
    #pragma unroll 1
    for (int j = 0; j < 24; ++j) {
        int w  = widx * 24 + j;
        int wy = w / 12, wx = w - (w / 12) * 12;

        uint4 Bv = wdfrag[(size_t)w * 32];       // dense B frags (L2)

        float pc[2][4];
        #pragma unroll
        for (int p = 0; p < 4; ++p) {
            int y = 2 * wy + (p >> 1);
            int x = 2 * wx + (p & 1);
            int base0 = g * IMG_STR + y * 28 + x;
            int base1 = base0 + 8 * IMG_STR;

            // C initialized with k=24 fixup (hi+lo reconstructs the pixel)
            float v0 = __uint_as_float(s_hi[base0 + 116])
                     + __uint_as_float(s_lo[base0 + 116]);
            float v1 = __uint_as_float(s_hi[base1 + 116])
                     + __uint_as_float(s_lo[base1 + 116]);
            float c[2][4];
            #pragma unroll
            for (int nt = 0; nt < 2; ++nt) {
                c[nt][0] = v0 * w24[nt][0];
                c[nt][1] = v0 * w24[nt][1];
                c[nt][2] = v1 * w24[nt][0];
                c[nt][3] = v1 * w24[nt][1];
            }

            #pragma unroll
            for (int s = 0; s < 3; ++s) {
                unsigned ah0 = s_hi[base0 + koffA[s]];
                unsigned ah1 = s_hi[base1 + koffA[s]];
                unsigned ah2 = s_hi[base0 + koffB[s]];
                unsigned ah3 = s_hi[base1 + koffB[s]];
                unsigned al0 = s_lo[base0 + koffA[s]];
                unsigned al1 = s_lo[base1 + koffA[s]];
                unsigned al2 = s_lo[base0 + koffB[s]];
                unsigned al3 = s_lo[base1 + koffB[s]];
                #pragma unroll
                for (int nt = 0; nt < 2; ++nt) {
                    MMA_TF32(c[nt][0], c[nt][1], c[nt][2], c[nt][3],
                             ah0, ah1, ah2, ah3,
                             bhi[nt][s][0], bhi[nt][s][1]);
                    MMA_TF32(c[nt][0], c[nt][1], c[nt][2], c[nt][3],
                             ah0, ah1, ah2, ah3,
                             blo[nt][s][0], blo[nt][s][1]);
                    MMA_TF32(c[nt][0], c[nt][1], c[nt][2], c[nt][3],
                             al0, al1, al2, al3,
                             bhi[nt][s][0], bhi[nt][s][1]);
                }
            }

            if (p == 0) {
                #pragma unroll
                for (int nt = 0; nt < 2; ++nt)
                    #pragma unroll
                    for (int e = 0; e < 4; ++e) pc[nt][e] = c[nt][e];
            } else {
                #pragma unroll
                for (int nt = 0; nt < 2; ++nt)
                    #pragma unroll
                    for (int e = 0; e < 4; ++e)
                        pc[nt][e] = fmaxf(pc[nt][e], c[nt][e]);
            }
        }

        // bias + relu in registers
        #pragma unroll
        for (int nt = 0; nt < 2; ++nt) {
            pc[nt][0] = fmaxf(pc[nt][0] + cbias[nt][0], 0.f);
            pc[nt][1] = fmaxf(pc[nt][1] + cbias[nt][1], 0.f);
            pc[nt][2] = fmaxf(pc[nt][2] + cbias[nt][0], 0.f);
            pc[nt][3] = fmaxf(pc[nt][3] + cbias[nt][1], 0.f);
        }

        // pack pooled frags -> fp16 A (16 img x 16 ch)
        unsigned a0 = pack_h2(pc[0][0], pc[0][1]);
        unsigned a1 = pack_h2(pc[0][2], pc[0][3]);
        unsigned a2 = pack_h2(pc[1][0], pc[1][1]);
        unsigned a3 = pack_h2(pc[1][2], pc[1][3]);

        MMA_F16(dc[0][0], dc[0][1], dc[0][2], dc[0][3],
                a0, a1, a2, a3, Bv.x, Bv.y);
        MMA_F16(dc[1][0], dc[1][1], dc[1][2], dc[1][3],
                a0, a1, a2, a3, Bv.z, Bv.w);
    }

    // ---- reduce 12 warps' partial dense C, bias, log_softmax ----
    __syncthreads();                        // everyone done reading image planes
    float* s_red = (float*)s_mem;           // [12][16 img][16 out]
    float* s_log = (float*)s_mem + 12 * 256;
    {
        float* wr = s_red + warp * 256;
        wr[ g      * 16 + 2 * tid    ] = dc[0][0];
        wr[ g      * 16 + 2 * tid + 1] = dc[0][1];
        wr[(g + 8) * 16 + 2 * tid    ] = dc[0][2];
        wr[(g + 8) * 16 + 2 * tid + 1] = dc[0][3];
        wr[ g      * 16 + 8 + 2 * tid    ] = dc[1][0];
        wr[ g      * 16 + 8 + 2 * tid + 1] = dc[1][1];
        wr[(g + 8) * 16 + 8 + 2 * tid    ] = dc[1][2];
        wr[(g + 8) * 16 + 8 + 2 * tid + 1] = dc[1][3];
    }
    __syncthreads();

    if (t < 160) {
        int img = t / 10, o = t % 10;
        float s = 0.f;
        #pragma unroll
        for (int wp = 0; wp < 12; ++wp) s += s_red[wp * 256 + img * 16 + o];
        s_log[t] = s + P[OFF_BDENSE + o];
    }
    __syncthreads();

    if (t < 16) {
        float v[10], m = -1e30f;
        #pragma unroll
        for (int o = 0; o < 10; ++o) { v[o] = s_log[t * 10 + o]; m = fmaxf(m, v[o]); }
        float su = 0.f;
        #pragma unroll
        for (int o = 0; o < 10; ++o) su += expf(v[o] - m);
        float ls = m + logf(su);
        float* op = out + ((size_t)init * 128 + n0 + t) * 10;
        #pragma unroll
        for (int o = 0; o < 10; ++o) op[o] = v[o] - ls;
    }
}

// ============================================================================
extern "C" void kernel_launch(void* const* d_in, const int* in_sizes, int n_in,
                              void* d_out, int out_size)
{
    const float* params = (const float*)d_in[0];   // [64, 46922]
    const float* batch  = (const float*)d_in[1];   // [128, 1, 28, 28]
    float* out          = (float*)d_out;           // [64, 128, 10]

    cudaFuncSetAttribute(fused_kernel,
                         cudaFuncAttributeMaxDynamicSharedMemorySize, K1_SMEM);

    prep_wd_kernel<<<128, 256>>>(params);
    fused_kernel<<<512, K1_THREADS, K1_SMEM>>>(params, batch, out);
}

// round 10
// speedup vs baseline: 1.3576x; 1.3576x over previous
#include <cuda_runtime.h>
#include <cuda_fp16.h>
#include <math.h>

#define NUM_INITS 64
#define PSTRIDE   46922
#define OFF_WDENSE 832
#define OFF_BDENSE 46912

// Dense weights pre-swizzled into fp16 B-fragment order:
// [init][wg(2)][w(144)][lane(32)] -> uint4 {b0_nt0, b1_nt0, b0_nt1, b1_nt1}
__device__ uint4 g_wdh[128 * 144 * 32];   // 9.4 MB

__device__ __forceinline__ unsigned pack_h2(float lo, float hi) {
    __half2 h = __floats2half2_rn(lo, hi);
    return *(unsigned*)&h;
}

__device__ __forceinline__ unsigned tf32_of(float x) {
    unsigned r;
    asm("cvt.rna.tf32.f32 %0, %1;" : "=r"(r) : "f"(x));
    return r;
}

#define MMA_TF32(c0,c1,c2,c3,a0,a1,a2,a3,b0,b1) \
    asm("mma.sync.aligned.m16n8k8.row.col.f32.tf32.tf32.f32 " \
        "{%0,%1,%2,%3}, {%4,%5,%6,%7}, {%8,%9}, {%0,%1,%2,%3};" \
        : "+f"(c0), "+f"(c1), "+f"(c2), "+f"(c3) \
        : "r"(a0), "r"(a1), "r"(a2), "r"(a3), "r"(b0), "r"(b1))

#define MMA_F16(c0,c1,c2,c3,a0,a1,a2,a3,b0,b1) \
    asm("mma.sync.aligned.m16n8k16.row.col.f32.f16.f16.f32 " \
        "{%0,%1,%2,%3}, {%4,%5,%6,%7}, {%8,%9}, {%0,%1,%2,%3};" \
        : "+f"(c0), "+f"(c1), "+f"(c2), "+f"(c3) \
        : "r"(a0), "r"(a1), "r"(a2), "r"(a3), "r"(b0), "r"(b1))

// ============================================================================
// Prep: swizzle dense weights -> fp16 B fragments. grid 128 = (init, wg)
// ============================================================================
__global__ void __launch_bounds__(256)
prep_wd_kernel(const float* __restrict__ params)
{
    const int blk  = blockIdx.x;          // init*2 + wg
    const int init = blk >> 1;
    const int wg   = blk & 1;
    const float* __restrict__ W = params + (size_t)init * PSTRIDE + OFF_WDENSE;

    for (int u = threadIdx.x; u < 144 * 32; u += 256) {
        int w    = u >> 5;
        int lane = u & 31;
        int g    = lane >> 2;
        int tb   = lane & 3;
        int ch0  = wg * 16 + 2 * tb;

        #define WD(o, ch) W[(size_t)(o) * 4608 + (ch) * 144 + w]
        unsigned b0n0 = pack_h2(WD(g, ch0),     WD(g, ch0 + 1));
        unsigned b1n0 = pack_h2(WD(g, ch0 + 8), WD(g, ch0 + 9));
        unsigned b0n1 = 0, b1n1 = 0;
        if (g + 8 < 10) {
            b0n1 = pack_h2(WD(g + 8, ch0),     WD(g + 8, ch0 + 1));
            b1n1 = pack_h2(WD(g + 8, ch0 + 8), WD(g + 8, ch0 + 9));
        }
        #undef WD
        g_wdh[(size_t)(blk * 144 + w) * 32 + lane] =
            make_uint4(b0n0, b1n0, b0n1, b1n1);
    }
}

// ============================================================================
// Fused: conv5x5 (tf32 2-pass: ah*bhi + ah*blo) + pool + bias + relu
//        + dense(fp16 mma) + log_softmax
// grid 512 = (init, img-tile of 16), 384 threads = 12 warps
// ============================================================================
#define IMG_STR 788
#define K1_THREADS 384
#define K1_SMEM (2 * 16 * IMG_STR * 4)    // hi plane + raw fp32 plane = 100864 B

__global__ void __launch_bounds__(K1_THREADS, 2)
fused_kernel(const float* __restrict__ params,
             const float* __restrict__ batch,
             float* __restrict__ out)
{
    extern __shared__ unsigned s_mem[];
    unsigned* s_hi = s_mem;                     // [16][788] tf32 hi bits
    float*    s_fp = (float*)(s_mem + 16 * IMG_STR);  // [16][788] raw pixels

    const int blk  = blockIdx.x;
    const int init = blk >> 3;
    const int n0   = (blk & 7) * 16;
    const int t    = threadIdx.x;
    const int warp = t >> 5;
    const int lane = t & 31;
    const int g    = lane >> 2;   // 0..7
    const int tid  = lane & 3;    // 0..3

    const float* __restrict__ P = params + (size_t)init * PSTRIDE;

    // ---- stage 16 images: tf32-hi plane + raw plane ----
    for (int u = t; u < 16 * 196; u += K1_THREADS) {
        int img = u / 196, q = u - img * 196;
        float4 v = ((const float4*)(batch + (size_t)(n0 + img) * 784))[q];
        uint4 hi;
        hi.x = tf32_of(v.x); hi.y = tf32_of(v.y);
        hi.z = tf32_of(v.z); hi.w = tf32_of(v.w);
        ((uint4*)(s_hi + img * IMG_STR))[q]  = hi;
        ((float4*)(s_fp + img * IMG_STR))[q] = v;
    }
    __syncthreads();

    const int wg     = warp / 6;          // channels wg*16..+15
    const int widx   = warp % 6;          // windows widx*24..+23
    const int chbase = wg * 16;

    // ---- conv B fragments (weights), split hi/lo ----
    unsigned bhi[2][3][2], blo[2][3][2];
    #pragma unroll
    for (int nt = 0; nt < 2; ++nt) {
        int ch = chbase + nt * 8 + g;
        #pragma unroll
        for (int s = 0; s < 3; ++s) {
            float w0 = P[ch * 25 + s * 8 + tid];
            float w1 = P[ch * 25 + s * 8 + tid + 4];
            unsigned h0 = tf32_of(w0), h1 = tf32_of(w1);
            bhi[nt][s][0] = h0;
            bhi[nt][s][1] = h1;
            blo[nt][s][0] = tf32_of(w0 - __uint_as_float(h0));
            blo[nt][s][1] = tf32_of(w1 - __uint_as_float(h1));
        }
    }
    float w24[2][2], cbias[2][2];
    #pragma unroll
    for (int nt = 0; nt < 2; ++nt)
        #pragma unroll
        for (int jj = 0; jj < 2; ++jj) {
            int ch = chbase + nt * 8 + 2 * tid + jj;
            w24[nt][jj]   = P[ch * 25 + 24];
            cbias[nt][jj] = P[800 + ch];
        }

    int koffA[3], koffB[3];
    #pragma unroll
    for (int s = 0; s < 3; ++s) {
        int ka = s * 8 + tid, kb = ka + 4;
        koffA[s] = (ka / 5) * 28 + (ka % 5);
        koffB[s] = (kb / 5) * 28 + (kb % 5);
    }

    const uint4* __restrict__ wdfrag =
        g_wdh + (size_t)((init * 2 + wg) * 144) * 32 + lane;

    // persistent dense accumulators
    float dc[2][4];
    #pragma unroll
    for (int q = 0; q < 4; ++q) { dc[0][q] = 0.f; dc[1][q] = 0.f; }

    // ---- main loop over this warp's 24 pool windows ----
    #pragma unroll 1
    for (int j = 0; j < 24; ++j) {
        int w  = widx * 24 + j;
        int wy = w / 12, wx = w - (w / 12) * 12;

        uint4 Bv = wdfrag[(size_t)w * 32];       // dense B frags (L2)

        float pc[2][4];
        #pragma unroll
        for (int p = 0; p < 4; ++p) {
            int y = 2 * wy + (p >> 1);
            int x = 2 * wx + (p & 1);
            int base0 = g * IMG_STR + y * 28 + x;
            int base1 = base0 + 8 * IMG_STR;

            // C initialized with k=24 fixup from the exact raw pixel
            float v0 = s_fp[base0 + 116];
            float v1 = s_fp[base1 + 116];
            float c[2][4];
            #pragma unroll
            for (int nt = 0; nt < 2; ++nt) {
                c[nt][0] = v0 * w24[nt][0];
                c[nt][1] = v0 * w24[nt][1];
                c[nt][2] = v1 * w24[nt][0];
                c[nt][3] = v1 * w24[nt][1];
            }

            #pragma unroll
            for (int s = 0; s < 3; ++s) {
                unsigned ah0 = s_hi[base0 + koffA[s]];
                unsigned ah1 = s_hi[base1 + koffA[s]];
                unsigned ah2 = s_hi[base0 + koffB[s]];
                unsigned ah3 = s_hi[base1 + koffB[s]];
                #pragma unroll
                for (int nt = 0; nt < 2; ++nt) {
                    MMA_TF32(c[nt][0], c[nt][1], c[nt][2], c[nt][3],
                             ah0, ah1, ah2, ah3,
                             bhi[nt][s][0], bhi[nt][s][1]);
                    MMA_TF32(c[nt][0], c[nt][1], c[nt][2], c[nt][3],
                             ah0, ah1, ah2, ah3,
                             blo[nt][s][0], blo[nt][s][1]);
                }
            }

            if (p == 0) {
                #pragma unroll
                for (int nt = 0; nt < 2; ++nt)
                    #pragma unroll
                    for (int e = 0; e < 4; ++e) pc[nt][e] = c[nt][e];
            } else {
                #pragma unroll
                for (int nt = 0; nt < 2; ++nt)
                    #pragma unroll
                    for (int e = 0; e < 4; ++e)
                        pc[nt][e] = fmaxf(pc[nt][e], c[nt][e]);
            }
        }

        // bias + relu in registers
        #pragma unroll
        for (int nt = 0; nt < 2; ++nt) {
            pc[nt][0] = fmaxf(pc[nt][0] + cbias[nt][0], 0.f);
            pc[nt][1] = fmaxf(pc[nt][1] + cbias[nt][1], 0.f);
            pc[nt][2] = fmaxf(pc[nt][2] + cbias[nt][0], 0.f);
            pc[nt][3] = fmaxf(pc[nt][3] + cbias[nt][1], 0.f);
        }

        // pack pooled frags -> fp16 A (16 img x 16 ch)
        unsigned a0 = pack_h2(pc[0][0], pc[0][1]);
        unsigned a1 = pack_h2(pc[0][2], pc[0][3]);
        unsigned a2 = pack_h2(pc[1][0], pc[1][1]);
        unsigned a3 = pack_h2(pc[1][2], pc[1][3]);

        MMA_F16(dc[0][0], dc[0][1], dc[0][2], dc[0][3],
                a0, a1, a2, a3, Bv.x, Bv.y);
        MMA_F16(dc[1][0], dc[1][1], dc[1][2], dc[1][3],
                a0, a1, a2, a3, Bv.z, Bv.w);
    }

    // ---- reduce 12 warps' partial dense C, bias, log_softmax ----
    __syncthreads();                        // everyone done reading image planes
    float* s_red = (float*)s_mem;           // [12][16 img][16 out]
    float* s_log = (float*)s_mem + 12 * 256;
    {
        float* wr = s_red + warp * 256;
        wr[ g      * 16 + 2 * tid    ] = dc[0][0];
        wr[ g      * 16 + 2 * tid + 1] = dc[0][1];
        wr[(g + 8) * 16 + 2 * tid    ] = dc[0][2];
        wr[(g + 8) * 16 + 2 * tid + 1] = dc[0][3];
        wr[ g      * 16 + 8 + 2 * tid    ] = dc[1][0];
        wr[ g      * 16 + 8 + 2 * tid + 1] = dc[1][1];
        wr[(g + 8) * 16 + 8 + 2 * tid    ] = dc[1][2];
        wr[(g + 8) * 16 + 8 + 2 * tid + 1] = dc[1][3];
    }
    __syncthreads();

    if (t < 160) {
        int img = t / 10, o = t % 10;
        float s = 0.f;
        #pragma unroll
        for (int wp = 0; wp < 12; ++wp) s += s_red[wp * 256 + img * 16 + o];
        s_log[t] = s + P[OFF_BDENSE + o];
    }
    __syncthreads();

    if (t < 16) {
        float v[10], m = -1e30f;
        #pragma unroll
        for (int o = 0; o < 10; ++o) { v[o] = s_log[t * 10 + o]; m = fmaxf(m, v[o]); }
        float su = 0.f;
        #pragma unroll
        for (int o = 0; o < 10; ++o) su += expf(v[o] - m);
        float ls = m + logf(su);
        float* op = out + ((size_t)init * 128 + n0 + t) * 10;
        #pragma unroll
        for (int o = 0; o < 10; ++o) op[o] = v[o] - ls;
    }
}

// ============================================================================
extern "C" void kernel_launch(void* const* d_in, const int* in_sizes, int n_in,
                              void* d_out, int out_size)
{
    const float* params = (const float*)d_in[0];   // [64, 46922]
    const float* batch  = (const float*)d_in[1];   // [128, 1, 28, 28]
    float* out          = (float*)d_out;           // [64, 128, 10]

    cudaFuncSetAttribute(fused_kernel,
                         cudaFuncAttributeMaxDynamicSharedMemorySize, K1_SMEM);

    prep_wd_kernel<<<128, 256>>>(params);
    fused_kernel<<<512, K1_THREADS, K1_SMEM>>>(params, batch, out);
}

// round 11
// speedup vs baseline: 1.8825x; 1.3866x over previous
#include <cuda_runtime.h>
#include <cuda_fp16.h>
#include <math.h>

#define NUM_INITS 64
#define PSTRIDE   46922
#define OFF_WDENSE 832
#define OFF_BDENSE 46912

// Dense weights pre-swizzled into fp16 B-fragment order:
// [init][wg(2)][w(144)][lane(32)] -> uint4 {b0_nt0, b1_nt0, b0_nt1, b1_nt1}
__device__ uint4 g_wdh[128 * 144 * 32];   // 9.4 MB

__device__ __forceinline__ unsigned pack_h2(float lo, float hi) {
    __half2 h = __floats2half2_rn(lo, hi);
    return *(unsigned*)&h;
}

__device__ __forceinline__ unsigned tf32_of(float x) {
    unsigned r;
    asm("cvt.rna.tf32.f32 %0, %1;" : "=r"(r) : "f"(x));
    return r;
}

#define MMA_TF32(c0,c1,c2,c3,a0,a1,a2,a3,b0,b1) \
    asm("mma.sync.aligned.m16n8k8.row.col.f32.tf32.tf32.f32 " \
        "{%0,%1,%2,%3}, {%4,%5,%6,%7}, {%8,%9}, {%0,%1,%2,%3};" \
        : "+f"(c0), "+f"(c1), "+f"(c2), "+f"(c3) \
        : "r"(a0), "r"(a1), "r"(a2), "r"(a3), "r"(b0), "r"(b1))

#define MMA_F16(c0,c1,c2,c3,a0,a1,a2,a3,b0,b1) \
    asm("mma.sync.aligned.m16n8k16.row.col.f32.f16.f16.f32 " \
        "{%0,%1,%2,%3}, {%4,%5,%6,%7}, {%8,%9}, {%0,%1,%2,%3};" \
        : "+f"(c0), "+f"(c1), "+f"(c2), "+f"(c3) \
        : "r"(a0), "r"(a1), "r"(a2), "r"(a3), "r"(b0), "r"(b1))

// ============================================================================
// Prep: swizzle dense weights -> fp16 B fragments. grid 128 = (init, wg)
// ============================================================================
__global__ void __launch_bounds__(256)
prep_wd_kernel(const float* __restrict__ params)
{
    const int blk  = blockIdx.x;          // init*2 + wg
    const int init = blk >> 1;
    const int wg   = blk & 1;
    const float* __restrict__ W = params + (size_t)init * PSTRIDE + OFF_WDENSE;

    for (int u = threadIdx.x; u < 144 * 32; u += 256) {
        int w    = u >> 5;
        int lane = u & 31;
        int g    = lane >> 2;
        int tb   = lane & 3;
        int ch0  = wg * 16 + 2 * tb;

        #define WD(o, ch) W[(size_t)(o) * 4608 + (ch) * 144 + w]
        unsigned b0n0 = pack_h2(WD(g, ch0),     WD(g, ch0 + 1));
        unsigned b1n0 = pack_h2(WD(g, ch0 + 8), WD(g, ch0 + 9));
        unsigned b0n1 = 0, b1n1 = 0;
        if (g + 8 < 10) {
            b0n1 = pack_h2(WD(g + 8, ch0),     WD(g + 8, ch0 + 1));
            b1n1 = pack_h2(WD(g + 8, ch0 + 8), WD(g + 8, ch0 + 9));
        }
        #undef WD
        g_wdh[(size_t)(blk * 144 + w) * 32 + lane] =
            make_uint4(b0n0, b1n0, b0n1, b1n1);
    }
}

// ============================================================================
// Fused: conv5x5 (tf32 1-pass) + pool + bias + relu + dense(fp16 mma)
//        + log_softmax
// grid 512 = (init, img-tile of 16), 384 threads = 12 warps
// ============================================================================
#define IMG_STR 788
#define K1_THREADS 384
#define K1_SMEM (2 * 16 * IMG_STR * 4)    // hi plane + raw fp32 plane = 100864 B

__global__ void __launch_bounds__(K1_THREADS, 2)
fused_kernel(const float* __restrict__ params,
             const float* __restrict__ batch,
             float* __restrict__ out)
{
    extern __shared__ unsigned s_mem[];
    unsigned* s_hi = s_mem;                     // [16][788] tf32 hi bits
    float*    s_fp = (float*)(s_mem + 16 * IMG_STR);  // [16][788] raw pixels

    const int blk  = blockIdx.x;
    const int init = blk >> 3;
    const int n0   = (blk & 7) * 16;
    const int t    = threadIdx.x;
    const int warp = t >> 5;
    const int lane = t & 31;
    const int g    = lane >> 2;   // 0..7
    const int tid  = lane & 3;    // 0..3

    const float* __restrict__ P = params + (size_t)init * PSTRIDE;

    // ---- stage 16 images: tf32-hi plane + raw plane ----
    for (int u = t; u < 16 * 196; u += K1_THREADS) {
        int img = u / 196, q = u - img * 196;
        float4 v = ((const float4*)(batch + (size_t)(n0 + img) * 784))[q];
        uint4 hi;
        hi.x = tf32_of(v.x); hi.y = tf32_of(v.y);
        hi.z = tf32_of(v.z); hi.w = tf32_of(v.w);
        ((uint4*)(s_hi + img * IMG_STR))[q]  = hi;
        ((float4*)(s_fp + img * IMG_STR))[q] = v;
    }
    __syncthreads();

    const int wg     = warp / 6;          // channels wg*16..+15
    const int widx   = warp % 6;          // windows widx*24..+23
    const int chbase = wg * 16;

    // ---- conv B fragments (weights, tf32-rounded) ----
    unsigned bhi[2][3][2];
    #pragma unroll
    for (int nt = 0; nt < 2; ++nt) {
        int ch = chbase + nt * 8 + g;
        #pragma unroll
        for (int s = 0; s < 3; ++s) {
            bhi[nt][s][0] = tf32_of(P[ch * 25 + s * 8 + tid]);
            bhi[nt][s][1] = tf32_of(P[ch * 25 + s * 8 + tid + 4]);
        }
    }
    float w24[2][2], cbias[2][2];
    #pragma unroll
    for (int nt = 0; nt < 2; ++nt)
        #pragma unroll
        for (int jj = 0; jj < 2; ++jj) {
            int ch = chbase + nt * 8 + 2 * tid + jj;
            w24[nt][jj]   = P[ch * 25 + 24];
            cbias[nt][jj] = P[800 + ch];
        }

    int koffA[3], koffB[3];
    #pragma unroll
    for (int s = 0; s < 3; ++s) {
        int ka = s * 8 + tid, kb = ka + 4;
        koffA[s] = (ka / 5) * 28 + (ka % 5);
        koffB[s] = (kb / 5) * 28 + (kb % 5);
    }

    const uint4* __restrict__ wdfrag =
        g_wdh + (size_t)((init * 2 + wg) * 144) * 32 + lane;

    // persistent dense accumulators
    float dc[2][4];
    #pragma unroll
    for (int q = 0; q < 4; ++q) { dc[0][q] = 0.f; dc[1][q] = 0.f; }

    // ---- main loop over this warp's 24 pool windows ----
    #pragma unroll 1
    for (int j = 0; j < 24; ++j) {
        int w  = widx * 24 + j;
        int wy = w / 12, wx = w - (w / 12) * 12;

        uint4 Bv = wdfrag[(size_t)w * 32];       // dense B frags (L2)

        float pc[2][4];
        #pragma unroll
        for (int p = 0; p < 4; ++p) {
            int y = 2 * wy + (p >> 1);
            int x = 2 * wx + (p & 1);
            int base0 = g * IMG_STR + y * 28 + x;
            int base1 = base0 + 8 * IMG_STR;

            // C initialized with k=24 fixup from the exact raw pixel
            float v0 = s_fp[base0 + 116];
            float v1 = s_fp[base1 + 116];
            float c[2][4];
            #pragma unroll
            for (int nt = 0; nt < 2; ++nt) {
                c[nt][0] = v0 * w24[nt][0];
                c[nt][1] = v0 * w24[nt][1];
                c[nt][2] = v1 * w24[nt][0];
                c[nt][3] = v1 * w24[nt][1];
            }

            #pragma unroll
            for (int s = 0; s < 3; ++s) {
                unsigned ah0 = s_hi[base0 + koffA[s]];
                unsigned ah1 = s_hi[base1 + koffA[s]];
                unsigned ah2 = s_hi[base0 + koffB[s]];
                unsigned ah3 = s_hi[base1 + koffB[s]];
                #pragma unroll
                for (int nt = 0; nt < 2; ++nt) {
                    MMA_TF32(c[nt][0], c[nt][1], c[nt][2], c[nt][3],
                             ah0, ah1, ah2, ah3,
                             bhi[nt][s][0], bhi[nt][s][1]);
                }
            }

            if (p == 0) {
                #pragma unroll
                for (int nt = 0; nt < 2; ++nt)
                    #pragma unroll
                    for (int e = 0; e < 4; ++e) pc[nt][e] = c[nt][e];
            } else {
                #pragma unroll
                for (int nt = 0; nt < 2; ++nt)
                    #pragma unroll
                    for (int e = 0; e < 4; ++e)
                        pc[nt][e] = fmaxf(pc[nt][e], c[nt][e]);
            }
        }

        // bias + relu in registers
        #pragma unroll
        for (int nt = 0; nt < 2; ++nt) {
            pc[nt][0] = fmaxf(pc[nt][0] + cbias[nt][0], 0.f);
            pc[nt][1] = fmaxf(pc[nt][1] + cbias[nt][1], 0.f);
            pc[nt][2] = fmaxf(pc[nt][2] + cbias[nt][0], 0.f);
            pc[nt][3] = fmaxf(pc[nt][3] + cbias[nt][1], 0.f);
        }

        // pack pooled frags -> fp16 A (16 img x 16 ch)
        unsigned a0 = pack_h2(pc[0][0], pc[0][1]);
        unsigned a1 = pack_h2(pc[0][2], pc[0][3]);
        unsigned a2 = pack_h2(pc[1][0], pc[1][1]);
        unsigned a3 = pack_h2(pc[1][2], pc[1][3]);

        MMA_F16(dc[0][0], dc[0][1], dc[0][2], dc[0][3],
                a0, a1, a2, a3, Bv.x, Bv.y);
        MMA_F16(dc[1][0], dc[1][1], dc[1][2], dc[1][3],
                a0, a1, a2, a3, Bv.z, Bv.w);
    }

    // ---- reduce 12 warps' partial dense C, bias, log_softmax ----
    __syncthreads();                        // everyone done reading image planes
    float* s_red = (float*)s_mem;           // [12][16 img][16 out]
    float* s_log = (float*)s_mem + 12 * 256;
    {
        float* wr = s_red + warp * 256;
        wr[ g      * 16 + 2 * tid    ] = dc[0][0];
        wr[ g      * 16 + 2 * tid + 1] = dc[0][1];
        wr[(g + 8) * 16 + 2 * tid    ] = dc[0][2];
        wr[(g + 8) * 16 + 2 * tid + 1] = dc[0][3];
        wr[ g      * 16 + 8 + 2 * tid    ] = dc[1][0];
        wr[ g      * 16 + 8 + 2 * tid + 1] = dc[1][1];
        wr[(g + 8) * 16 + 8 + 2 * tid    ] = dc[1][2];
        wr[(g + 8) * 16 + 8 + 2 * tid + 1] = dc[1][3];
    }
    __syncthreads();

    if (t < 160) {
        int img = t / 10, o = t % 10;
        float s = 0.f;
        #pragma unroll
        for (int wp = 0; wp < 12; ++wp) s += s_red[wp * 256 + img * 16 + o];
        s_log[t] = s + P[OFF_BDENSE + o];
    }
    __syncthreads();

    if (t < 16) {
        float v[10], m = -1e30f;
        #pragma unroll
        for (int o = 0; o < 10; ++o) { v[o] = s_log[t * 10 + o]; m = fmaxf(m, v[o]); }
        float su = 0.f;
        #pragma unroll
        for (int o = 0; o < 10; ++o) su += expf(v[o] - m);
        float ls = m + logf(su);
        float* op = out + ((size_t)init * 128 + n0 + t) * 10;
        #pragma unroll
        for (int o = 0; o < 10; ++o) op[o] = v[o] - ls;
    }
}

// ============================================================================
extern "C" void kernel_launch(void* const* d_in, const int* in_sizes, int n_in,
                              void* d_out, int out_size)
{
    const float* params = (const float*)d_in[0];   // [64, 46922]
    const float* batch  = (const float*)d_in[1];   // [128, 1, 28, 28]
    float* out          = (float*)d_out;           // [64, 128, 10]

    cudaFuncSetAttribute(fused_kernel,
                         cudaFuncAttributeMaxDynamicSharedMemorySize, K1_SMEM);

    prep_wd_kernel<<<128, 256>>>(params);
    fused_kernel<<<512, K1_THREADS, K1_SMEM>>>(params, batch, out);
}

// round 12
// speedup vs baseline: 2.4324x; 1.2921x over previous
#include <cuda_runtime.h>
#include <cuda_fp16.h>
#include <math.h>

#define NUM_INITS 64
#define PSTRIDE   46922
#define OFF_WDENSE 832
#define OFF_BDENSE 46912

// Dense weights pre-swizzled into fp16 B-fragment order:
// [init][wg(2)][w(144)][lane(32)] -> uint4 {b0_nt0, b1_nt0, b0_nt1, b1_nt1}
__device__ uint4 g_wdh[128 * 144 * 32];   // 9.4 MB

__device__ __forceinline__ unsigned pack_h2(float lo, float hi) {
    __half2 h = __floats2half2_rn(lo, hi);
    return *(unsigned*)&h;
}

#define MMA_F16(c0,c1,c2,c3,a0,a1,a2,a3,b0,b1) \
    asm("mma.sync.aligned.m16n8k16.row.col.f32.f16.f16.f32 " \
        "{%0,%1,%2,%3}, {%4,%5,%6,%7}, {%8,%9}, {%0,%1,%2,%3};" \
        : "+f"(c0), "+f"(c1), "+f"(c2), "+f"(c3) \
        : "r"(a0), "r"(a1), "r"(a2), "r"(a3), "r"(b0), "r"(b1))

// ============================================================================
// Prep: swizzle dense weights -> fp16 B fragments. grid 128 = (init, wg)
// ============================================================================
__global__ void __launch_bounds__(256)
prep_wd_kernel(const float* __restrict__ params)
{
    const int blk  = blockIdx.x;          // init*2 + wg
    const int init = blk >> 1;
    const int wg   = blk & 1;
    const float* __restrict__ W = params + (size_t)init * PSTRIDE + OFF_WDENSE;

    for (int u = threadIdx.x; u < 144 * 32; u += 256) {
        int w    = u >> 5;
        int lane = u & 31;
        int g    = lane >> 2;
        int tb   = lane & 3;
        int ch0  = wg * 16 + 2 * tb;

        #define WD(o, ch) W[(size_t)(o) * 4608 + (ch) * 144 + w]
        unsigned b0n0 = pack_h2(WD(g, ch0),     WD(g, ch0 + 1));
        unsigned b1n0 = pack_h2(WD(g, ch0 + 8), WD(g, ch0 + 9));
        unsigned b0n1 = 0, b1n1 = 0;
        if (g + 8 < 10) {
            b0n1 = pack_h2(WD(g + 8, ch0),     WD(g + 8, ch0 + 1));
            b1n1 = pack_h2(WD(g + 8, ch0 + 8), WD(g + 8, ch0 + 9));
        }
        #undef WD
        g_wdh[(size_t)(blk * 144 + w) * 32 + lane] =
            make_uint4(b0n0, b1n0, b0n1, b1n1);
    }
}

// ============================================================================
// Fused: conv5x5 (fp16 m16n8k16, all 25 taps in-MMA) + pool + bias + relu
//        + dense (fp16 mma) + log_softmax
// grid 512 = (init, img-tile of 16), 384 threads = 12 warps
// Two fp16 image planes (planeB shifted +1 pixel) give aligned half2 loads
// for both window-column parities.
// ============================================================================
#define IMG_H   792                        // halfs per image (784 + 8 pad)
#define IMG_W   396                        // 32-bit words per image
#define K1_THREADS 384
#define K1_SMEM (2 * 16 * IMG_H * 2)       // 2 planes * 16 img * 792 half = 50688 B

__global__ void __launch_bounds__(K1_THREADS, 2)
fused_kernel(const float* __restrict__ params,
             const float* __restrict__ batch,
             float* __restrict__ out)
{
    extern __shared__ __align__(16) unsigned s_mem[];
    __half*   pA  = (__half*)s_mem;                 // [16][792]
    __half*   pB  = (__half*)s_mem + 16 * IMG_H;    // [16][792], pixel c at c+1
    unsigned* pAu = (unsigned*)pA;
    unsigned* pBu = (unsigned*)pB;

    const int blk  = blockIdx.x;
    const int init = blk >> 3;
    const int n0   = (blk & 7) * 16;
    const int t    = threadIdx.x;
    const int warp = t >> 5;
    const int lane = t & 31;
    const int g    = lane >> 2;   // 0..7
    const int tid  = lane & 3;    // 0..3

    const float* __restrict__ P = params + (size_t)init * PSTRIDE;

    // ---- stage 16 images into two fp16 planes ----
    for (int u = t; u < 16 * 196; u += K1_THREADS) {
        int im = u / 196, q = u - im * 196;
        float4 v = ((const float4*)(batch + (size_t)(n0 + im) * 784))[q];
        pAu[im * IMG_W + 2 * q    ] = pack_h2(v.x, v.y);
        pAu[im * IMG_W + 2 * q + 1] = pack_h2(v.z, v.w);
        __half* pb = pB + im * IMG_H + 4 * q + 1;
        pb[0] = __float2half(v.x); pb[1] = __float2half(v.y);
        pb[2] = __float2half(v.z); pb[3] = __float2half(v.w);
    }
    // zero pads (so zero-weight MMA slots never read NaN garbage)
    for (int v = t; v < 128; v += K1_THREADS) {
        int im = v >> 3, r = v & 7;
        pA[im * IMG_H + 784 + r] = __float2half(0.f);
        pB[im * IMG_H + (r == 0 ? 0 : 784 + r)] = __float2half(0.f);
    }
    __syncthreads();

    const int wg     = warp / 6;          // channels wg*16..+15
    const int widx   = warp % 6;          // windows widx*24..+23
    const int chbase = wg * 16;

    // ---- k-slot permutation: pair q -> (ky, kx); pair covers (kx, kx+1) ----
    const int pky[2][8] = {{0,0,1,1,2,2,3,3},{4,4,0,1,2,3,4,0}};
    const int pkx[2][8] = {{0,2,0,2,0,2,0,2},{0,2,4,4,4,4,4,0}};

    int kwlo[2], kwhi[2];                  // word offsets for pairs q=tid, q=tid+4
    #pragma unroll
    for (int s = 0; s < 2; ++s) {
        kwlo[s] = pky[s][tid]     * 14 + (pkx[s][tid]     >> 1);
        kwhi[s] = pky[s][tid + 4] * 14 + (pkx[s][tid + 4] >> 1);
    }

    // ---- conv B fragments (fp16 weight pairs) ----
    unsigned bfr[2][2][2];   // [ntile][kstep][lo/hi pair]
    #pragma unroll
    for (int nt = 0; nt < 2; ++nt) {
        int base = (chbase + nt * 8 + g) * 25;
        #pragma unroll
        for (int s = 0; s < 2; ++s) {
            {   // pair q = tid
                int ky = pky[s][tid], kx = pkx[s][tid];
                float wl = P[base + ky * 5 + kx];
                float wh = (kx < 4) ? P[base + ky * 5 + kx + 1] : 0.f;
                bfr[nt][s][0] = pack_h2(wl, wh);
            }
            {   // pair q = tid+4 (dummy slot: s==1, q==7)
                int q = tid + 4;
                int ky = pky[s][q], kx = pkx[s][q];
                bool dum = (s == 1 && q == 7);
                float wl = dum ? 0.f : P[base + ky * 5 + kx];
                float wh = (!dum && kx < 4) ? P[base + ky * 5 + kx + 1] : 0.f;
                bfr[nt][s][1] = pack_h2(wl, wh);
            }
        }
    }
    float cbias[2][2];
    #pragma unroll
    for (int nt = 0; nt < 2; ++nt)
        #pragma unroll
        for (int jj = 0; jj < 2; ++jj)
            cbias[nt][jj] = P[800 + chbase + nt * 8 + 2 * tid + jj];

    const uint4* __restrict__ wdfrag =
        g_wdh + (size_t)((init * 2 + wg) * 144) * 32 + lane;

    // persistent dense accumulators
    float dc[2][4];
    #pragma unroll
    for (int q = 0; q < 4; ++q) { dc[0][q] = 0.f; dc[1][q] = 0.f; }

    // ---- main loop over this warp's 24 pool windows ----
    #pragma unroll 1
    for (int j = 0; j < 24; ++j) {
        int w  = widx * 24 + j;
        int wy = w / 12, wx = w - (w / 12) * 12;

        uint4 Bv = wdfrag[(size_t)w * 32];       // dense B frags (L2)

        float pc[2][4];
        #pragma unroll
        for (int p = 0; p < 4; ++p) {
            int dy = p >> 1, dx = p & 1;
            int rowoff = (2 * wy + dy) * 14 + wx + dx;  // +dx = planeB shift
            const unsigned* __restrict__ pl = dx ? pBu : pAu;
            int b0 = g * IMG_W + rowoff;
            int b1 = b0 + 8 * IMG_W;

            float c[2][4] = {{0.f,0.f,0.f,0.f},{0.f,0.f,0.f,0.f}};
            #pragma unroll
            for (int s = 0; s < 2; ++s) {
                unsigned a0 = pl[b0 + kwlo[s]];
                unsigned a1 = pl[b1 + kwlo[s]];
                unsigned a2 = pl[b0 + kwhi[s]];
                unsigned a3 = pl[b1 + kwhi[s]];
                MMA_F16(c[0][0], c[0][1], c[0][2], c[0][3],
                        a0, a1, a2, a3, bfr[0][s][0], bfr[0][s][1]);
                MMA_F16(c[1][0], c[1][1], c[1][2], c[1][3],
                        a0, a1, a2, a3, bfr[1][s][0], bfr[1][s][1]);
            }

            if (p == 0) {
                #pragma unroll
                for (int nt = 0; nt < 2; ++nt)
                    #pragma unroll
                    for (int e = 0; e < 4; ++e) pc[nt][e] = c[nt][e];
            } else {
                #pragma unroll
                for (int nt = 0; nt < 2; ++nt)
                    #pragma unroll
                    for (int e = 0; e < 4; ++e)
                        pc[nt][e] = fmaxf(pc[nt][e], c[nt][e]);
            }
        }

        // bias + relu in registers
        #pragma unroll
        for (int nt = 0; nt < 2; ++nt) {
            pc[nt][0] = fmaxf(pc[nt][0] + cbias[nt][0], 0.f);
            pc[nt][1] = fmaxf(pc[nt][1] + cbias[nt][1], 0.f);
            pc[nt][2] = fmaxf(pc[nt][2] + cbias[nt][0], 0.f);
            pc[nt][3] = fmaxf(pc[nt][3] + cbias[nt][1], 0.f);
        }

        // pack pooled frags -> fp16 A (16 img x 16 ch)
        unsigned a0 = pack_h2(pc[0][0], pc[0][1]);
        unsigned a1 = pack_h2(pc[0][2], pc[0][3]);
        unsigned a2 = pack_h2(pc[1][0], pc[1][1]);
        unsigned a3 = pack_h2(pc[1][2], pc[1][3]);

        MMA_F16(dc[0][0], dc[0][1], dc[0][2], dc[0][3],
                a0, a1, a2, a3, Bv.x, Bv.y);
        MMA_F16(dc[1][0], dc[1][1], dc[1][2], dc[1][3],
                a0, a1, a2, a3, Bv.z, Bv.w);
    }

    // ---- reduce 12 warps' partial dense C, bias, log_softmax ----
    __syncthreads();                        // everyone done reading image planes
    float* s_red = (float*)s_mem;           // [12][16 img][16 out]
    float* s_log = (float*)s_mem + 12 * 256;
    {
        float* wr = s_red + warp * 256;
        wr[ g      * 16 + 2 * tid    ] = dc[0][0];
        wr[ g      * 16 + 2 * tid + 1] = dc[0][1];
        wr[(g + 8) * 16 + 2 * tid    ] = dc[0][2];
        wr[(g + 8) * 16 + 2 * tid + 1] = dc[0][3];
        wr[ g      * 16 + 8 + 2 * tid    ] = dc[1][0];
        wr[ g      * 16 + 8 + 2 * tid + 1] = dc[1][1];
        wr[(g + 8) * 16 + 8 + 2 * tid    ] = dc[1][2];
        wr[(g + 8) * 16 + 8 + 2 * tid + 1] = dc[1][3];
    }
    __syncthreads();

    if (t < 160) {
        int img = t / 10, o = t % 10;
        float s = 0.f;
        #pragma unroll
        for (int wp = 0; wp < 12; ++wp) s += s_red[wp * 256 + img * 16 + o];
        s_log[t] = s + P[OFF_BDENSE + o];
    }
    __syncthreads();

    if (t < 16) {
        float v[10], m = -1e30f;
        #pragma unroll
        for (int o = 0; o < 10; ++o) { v[o] = s_log[t * 10 + o]; m = fmaxf(m, v[o]); }
        float su = 0.f;
        #pragma unroll
        for (int o = 0; o < 10; ++o) su += expf(v[o] - m);
        float ls = m + logf(su);
        float* op = out + ((size_t)init * 128 + n0 + t) * 10;
        #pragma unroll
        for (int o = 0; o < 10; ++o) op[o] = v[o] - ls;
    }
}

// ============================================================================
extern "C" void kernel_launch(void* const* d_in, const int* in_sizes, int n_in,
                              void* d_out, int out_size)
{
    const float* params = (const float*)d_in[0];   // [64, 46922]
    const float* batch  = (const float*)d_in[1];   // [128, 1, 28, 28]
    float* out          = (float*)d_out;           // [64, 128, 10]

    cudaFuncSetAttribute(fused_kernel,
                         cudaFuncAttributeMaxDynamicSharedMemorySize, K1_SMEM);

    prep_wd_kernel<<<128, 256>>>(params);
    fused_kernel<<<512, K1_THREADS, K1_SMEM>>>(params, batch, out);
}

// round 13
// speedup vs baseline: 2.7899x; 1.1470x over previous
#include <cuda_runtime.h>
#include <cuda_fp16.h>
#include <math.h>

#define NUM_INITS 64
#define PSTRIDE   46922
#define OFF_WDENSE 832
#define OFF_BDENSE 46912

// Dense weights pre-swizzled into fp16 B-fragment order:
// [init][wg(2)][w(144)][lane(32)] -> uint4 {b0_nt0, b1_nt0, b0_nt1, b1_nt1}
__device__ uint4 g_wdh[128 * 144 * 32];   // 9.4 MB

__device__ __forceinline__ unsigned pack_h2(float lo, float hi) {
    __half2 h = __floats2half2_rn(lo, hi);
    return *(unsigned*)&h;
}

#define MMA_F16(c0,c1,c2,c3,a0,a1,a2,a3,b0,b1) \
    asm("mma.sync.aligned.m16n8k16.row.col.f32.f16.f16.f32 " \
        "{%0,%1,%2,%3}, {%4,%5,%6,%7}, {%8,%9}, {%0,%1,%2,%3};" \
        : "+f"(c0), "+f"(c1), "+f"(c2), "+f"(c3) \
        : "r"(a0), "r"(a1), "r"(a2), "r"(a3), "r"(b0), "r"(b1))

// ============================================================================
// Prep: swizzle dense weights -> fp16 B fragments, COALESCED reads.
// grid 128 = (init, wg), 256 threads; warp = fragment role, lanes sweep w.
// ============================================================================
__global__ void __launch_bounds__(256)
prep_wd_kernel(const float* __restrict__ params)
{
    const int blk    = blockIdx.x;        // init*2 + wg
    const int init   = blk >> 1;
    const int wg     = blk & 1;
    const int warpid = threadIdx.x >> 5;
    const int lane   = threadIdx.x & 31;
    const float* __restrict__ W = params + (size_t)init * PSTRIDE + OFF_WDENSE;

    #pragma unroll 1
    for (int role = warpid; role < 32; role += 8) {
        int g   = role >> 2;
        int tb  = role & 3;
        int ch0 = wg * 16 + 2 * tb;
        #pragma unroll 1
        for (int w0 = 0; w0 < 144; w0 += 32) {
            int w = w0 + lane;
            if (w < 144) {
                #define WD(o, ch) W[(size_t)(o) * 4608 + (ch) * 144 + w]
                unsigned b0n0 = pack_h2(WD(g, ch0),     WD(g, ch0 + 1));
                unsigned b1n0 = pack_h2(WD(g, ch0 + 8), WD(g, ch0 + 9));
                unsigned b0n1 = 0, b1n1 = 0;
                if (g + 8 < 10) {
                    b0n1 = pack_h2(WD(g + 8, ch0),     WD(g + 8, ch0 + 1));
                    b1n1 = pack_h2(WD(g + 8, ch0 + 8), WD(g + 8, ch0 + 9));
                }
                #undef WD
                g_wdh[(size_t)(blk * 144 + w) * 32 + role] =
                    make_uint4(b0n0, b1n0, b0n1, b1n1);
            }
        }
    }
}

// ============================================================================
// Fused: conv5x5 (fp16 mma, 32 ch/warp) + pool + bias + relu + dense + softmax
// grid 512 = (init, img-tile of 16), 384 threads = 12 warps
// warp = pool-window ROW (wy = warp), j sweeps wx 0..11.
// ============================================================================
#define IMG_H   792
#define IMG_W   396
#define K1_THREADS 384
#define K1_SMEM (2 * 16 * IMG_H * 2)       // 50688 B

__global__ void __launch_bounds__(K1_THREADS, 2)
fused_kernel(const float* __restrict__ params,
             const float* __restrict__ batch,
             float* __restrict__ out)
{
    extern __shared__ __align__(16) unsigned s_mem[];
    __half*   pA  = (__half*)s_mem;                 // [16][792]
    __half*   pB  = (__half*)s_mem + 16 * IMG_H;    // [16][792], pixel c at c+1
    unsigned* pAu = (unsigned*)pA;
    unsigned* pBu = (unsigned*)pB;

    const int blk  = blockIdx.x;
    const int init = blk >> 3;
    const int n0   = (blk & 7) * 16;
    const int t    = threadIdx.x;
    const int warp = t >> 5;      // = wy (pool row)
    const int lane = t & 31;
    const int g    = lane >> 2;   // 0..7
    const int tid  = lane & 3;    // 0..3

    const float* __restrict__ P = params + (size_t)init * PSTRIDE;

    // ---- stage 16 images into two fp16 planes ----
    for (int u = t; u < 16 * 196; u += K1_THREADS) {
        int im = u / 196, q = u - im * 196;
        float4 v = ((const float4*)(batch + (size_t)(n0 + im) * 784))[q];
        pAu[im * IMG_W + 2 * q    ] = pack_h2(v.x, v.y);
        pAu[im * IMG_W + 2 * q + 1] = pack_h2(v.z, v.w);
        __half* pb = pB + im * IMG_H + 4 * q + 1;
        pb[0] = __float2half(v.x); pb[1] = __float2half(v.y);
        pb[2] = __float2half(v.z); pb[3] = __float2half(v.w);
    }
    for (int v = t; v < 128; v += K1_THREADS) {
        int im = v >> 3, r = v & 7;
        pA[im * IMG_H + 784 + r] = __float2half(0.f);
        pB[im * IMG_H + (r == 0 ? 0 : 784 + r)] = __float2half(0.f);
    }
    __syncthreads();

    // ---- k-slot permutation ----
    const int pky[2][8] = {{0,0,1,1,2,2,3,3},{4,4,0,1,2,3,4,0}};
    const int pkx[2][8] = {{0,2,0,2,0,2,0,2},{0,2,4,4,4,4,4,0}};
    int kwlo[2], kwhi[2];
    #pragma unroll
    for (int s = 0; s < 2; ++s) {
        kwlo[s] = pky[s][tid]     * 14 + (pkx[s][tid]     >> 1);
        kwhi[s] = pky[s][tid + 4] * 14 + (pkx[s][tid + 4] >> 1);
    }

    // ---- conv B fragments: ALL 32 channels (4 ntiles) ----
    unsigned bfr[4][2][2];
    #pragma unroll
    for (int nt = 0; nt < 4; ++nt) {
        int base = (nt * 8 + g) * 25;
        #pragma unroll
        for (int s = 0; s < 2; ++s) {
            {
                int ky = pky[s][tid], kx = pkx[s][tid];
                float wl = P[base + ky * 5 + kx];
                float wh = (kx < 4) ? P[base + ky * 5 + kx + 1] : 0.f;
                bfr[nt][s][0] = pack_h2(wl, wh);
            }
            {
                int q = tid + 4;
                int ky = pky[s][q], kx = pkx[s][q];
                bool dum = (s == 1 && q == 7);
                float wl = dum ? 0.f : P[base + ky * 5 + kx];
                float wh = (!dum && kx < 4) ? P[base + ky * 5 + kx + 1] : 0.f;
                bfr[nt][s][1] = pack_h2(wl, wh);
            }
        }
    }
    float cbias[4][2];
    #pragma unroll
    for (int nt = 0; nt < 4; ++nt)
        #pragma unroll
        for (int jj = 0; jj < 2; ++jj)
            cbias[nt][jj] = P[800 + nt * 8 + 2 * tid + jj];

    const uint4* __restrict__ wd0 =
        g_wdh + (size_t)((init * 2    ) * 144) * 32 + lane;
    const uint4* __restrict__ wd1 =
        g_wdh + (size_t)((init * 2 + 1) * 144) * 32 + lane;

    float dc[2][4];
    #pragma unroll
    for (int q = 0; q < 4; ++q) { dc[0][q] = 0.f; dc[1][q] = 0.f; }

    // ---- main loop: this warp's 12 windows (row wy=warp, wx=j) ----
    #pragma unroll 1
    for (int j = 0; j < 12; ++j) {
        int w = warp * 12 + j;
        uint4 Bv0 = wd0[(size_t)w * 32];   // dense B, ch 0-15
        uint4 Bv1 = wd1[(size_t)w * 32];   // dense B, ch 16-31

        float pc[4][4];
        #pragma unroll
        for (int p = 0; p < 4; ++p) {
            int dy = p >> 1, dx = p & 1;
            int rowoff = (2 * warp + dy) * 14 + j + dx;
            const unsigned* __restrict__ pl = dx ? pBu : pAu;
            int b0 = g * IMG_W + rowoff;
            int b1 = b0 + 8 * IMG_W;

            unsigned a[2][4];
            #pragma unroll
            for (int s = 0; s < 2; ++s) {
                a[s][0] = pl[b0 + kwlo[s]];
                a[s][1] = pl[b1 + kwlo[s]];
                a[s][2] = pl[b0 + kwhi[s]];
                a[s][3] = pl[b1 + kwhi[s]];
            }
            #pragma unroll
            for (int nt = 0; nt < 4; ++nt) {
                float c0 = 0.f, c1 = 0.f, c2 = 0.f, c3 = 0.f;
                MMA_F16(c0, c1, c2, c3,
                        a[0][0], a[0][1], a[0][2], a[0][3],
                        bfr[nt][0][0], bfr[nt][0][1]);
                MMA_F16(c0, c1, c2, c3,
                        a[1][0], a[1][1], a[1][2], a[1][3],
                        bfr[nt][1][0], bfr[nt][1][1]);
                if (p == 0) {
                    pc[nt][0] = c0; pc[nt][1] = c1;
                    pc[nt][2] = c2; pc[nt][3] = c3;
                } else {
                    pc[nt][0] = fmaxf(pc[nt][0], c0);
                    pc[nt][1] = fmaxf(pc[nt][1], c1);
                    pc[nt][2] = fmaxf(pc[nt][2], c2);
                    pc[nt][3] = fmaxf(pc[nt][3], c3);
                }
            }
        }

        // bias + relu
        #pragma unroll
        for (int nt = 0; nt < 4; ++nt) {
            pc[nt][0] = fmaxf(pc[nt][0] + cbias[nt][0], 0.f);
            pc[nt][1] = fmaxf(pc[nt][1] + cbias[nt][1], 0.f);
            pc[nt][2] = fmaxf(pc[nt][2] + cbias[nt][0], 0.f);
            pc[nt][3] = fmaxf(pc[nt][3] + cbias[nt][1], 0.f);
        }

        // dense: A = 16img x 32ch, two k-steps of 16
        unsigned a0 = pack_h2(pc[0][0], pc[0][1]);
        unsigned a1 = pack_h2(pc[0][2], pc[0][3]);
        unsigned a2 = pack_h2(pc[1][0], pc[1][1]);
        unsigned a3 = pack_h2(pc[1][2], pc[1][3]);
        unsigned a4 = pack_h2(pc[2][0], pc[2][1]);
        unsigned a5 = pack_h2(pc[2][2], pc[2][3]);
        unsigned a6 = pack_h2(pc[3][0], pc[3][1]);
        unsigned a7 = pack_h2(pc[3][2], pc[3][3]);

        MMA_F16(dc[0][0], dc[0][1], dc[0][2], dc[0][3],
                a0, a1, a2, a3, Bv0.x, Bv0.y);
        MMA_F16(dc[1][0], dc[1][1], dc[1][2], dc[1][3],
                a0, a1, a2, a3, Bv0.z, Bv0.w);
        MMA_F16(dc[0][0], dc[0][1], dc[0][2], dc[0][3],
                a4, a5, a6, a7, Bv1.x, Bv1.y);
        MMA_F16(dc[1][0], dc[1][1], dc[1][2], dc[1][3],
                a4, a5, a6, a7, Bv1.z, Bv1.w);
    }

    // ---- reduce 12 warps' partial dense C, bias, log_softmax ----
    __syncthreads();
    float* s_red = (float*)s_mem;           // [12][16 img][16 out]
    float* s_log = (float*)s_mem + 12 * 256;
    {
        float* wr = s_red + warp * 256;
        wr[ g      * 16 + 2 * tid    ] = dc[0][0];
        wr[ g      * 16 + 2 * tid + 1] = dc[0][1];
        wr[(g + 8) * 16 + 2 * tid    ] = dc[0][2];
        wr[(g + 8) * 16 + 2 * tid + 1] = dc[0][3];
        wr[ g      * 16 + 8 + 2 * tid    ] = dc[1][0];
        wr[ g      * 16 + 8 + 2 * tid + 1] = dc[1][1];
        wr[(g + 8) * 16 + 8 + 2 * tid    ] = dc[1][2];
        wr[(g + 8) * 16 + 8 + 2 * tid + 1] = dc[1][3];
    }
    __syncthreads();

    if (t < 160) {
        int img = t / 10, o = t % 10;
        float s = 0.f;
        #pragma unroll
        for (int wp = 0; wp < 12; ++wp) s += s_red[wp * 256 + img * 16 + o];
        s_log[t] = s + P[OFF_BDENSE + o];
    }
    __syncthreads();

    if (t < 16) {
        float v[10], m = -1e30f;
        #pragma unroll
        for (int o = 0; o < 10; ++o) { v[o] = s_log[t * 10 + o]; m = fmaxf(m, v[o]); }
        float su = 0.f;
        #pragma unroll
        for (int o = 0; o < 10; ++o) su += expf(v[o] - m);
        float ls = m + logf(su);
        float* op = out + ((size_t)init * 128 + n0 + t) * 10;
        #pragma unroll
        for (int o = 0; o < 10; ++o) op[o] = v[o] - ls;
    }
}

// ============================================================================
extern "C" void kernel_launch(void* const* d_in, const int* in_sizes, int n_in,
                              void* d_out, int out_size)
{
    const float* params = (const float*)d_in[0];   // [64, 46922]
    const float* batch  = (const float*)d_in[1];   // [128, 1, 28, 28]
    float* out          = (float*)d_out;           // [64, 128, 10]

    cudaFuncSetAttribute(fused_kernel,
                         cudaFuncAttributeMaxDynamicSharedMemorySize, K1_SMEM);

    prep_wd_kernel<<<128, 256>>>(params);
    fused_kernel<<<512, K1_THREADS, K1_SMEM>>>(params, batch, out);
}